// round 6
// baseline (speedup 1.0000x reference)
#include <cuda_runtime.h>
#include <cuda_bf16.h>

// ---------------------------------------------------------------------------
// Problem constants (fixed shapes)
constexpr int B    = 4;
constexpr int NPTS = 4096;
constexpr int MPTS = 4096;
constexpr int C    = 128;
constexpr int KNN  = 32;
constexpr float RAD2 = 0.12f * 0.12f;
constexpr int GC   = 8;          // grid cells per dim (cell 0.125 > r 0.12)
constexpr int NC   = GC*GC*GC;   // 512 cells per batch
constexpr float LOG2E = 1.4426950408889634f;

// Scratch (__device__ globals; allocation-free rule)
__device__ __align__(16) float g_QA[B*NPTS*C];    // ((a@Wq+bq-bk)@Wa+ba)*log2e
__device__ __align__(16) float g_AD[B*NPTS*C];    // a@Wd + bd
__device__ __align__(16) float g_KN[B*MPTS*2*C];  // row m: [KA'*log2e | ND]
__device__ int g_idx[B*NPTS*KNN];

// Spatial grid: set 0 = anchors, set 1 = neighbors. Index = (set*4+b)*NC + cell.
__device__ int g_cnt  [2*B*NC];
__device__ int g_start[2*B*NC];
__device__ int g_list [2*B*4096];

// f32x2 packed FMA (SASS FFMA2 — 2x fp32 rate; only reachable via PTX)
#define FFMA2(d, a, b, c) \
    asm("fma.rn.f32x2 %0, %1, %2, %3;" : "=l"(d) : "l"(a), "l"(b), "l"(c))
#define PACKF2(d, lo, hi) \
    asm("mov.b64 %0, {%1, %2};" : "=l"(d) : "f"(lo), "f"(hi))
#define UNPACKF2(lo, hi, in) \
    asm("mov.b64 {%0, %1}, %2;" : "=f"(lo), "=f"(hi) : "l"(in))

__device__ __forceinline__ float ex2f(float x) {
    float r; asm("ex2.approx.f32 %0, %1;" : "=f"(r) : "f"(x)); return r;
}

__device__ __forceinline__ void cell_coords(float x, float y, float z,
                                            int& cx, int& cy, int& cz) {
    cx = min(GC-1, max(0, (int)(x * (float)GC)));
    cy = min(GC-1, max(0, (int)(y * (float)GC)));
    cz = min(GC-1, max(0, (int)(z * (float)GC)));
}

// ---------------------------------------------------------------------------
// Fused grid build: one block per (set, batch). 512 threads, 4096 points.
// ---------------------------------------------------------------------------
__global__ void gridbuild_kernel(const float* __restrict__ anchor,
                                 const float* __restrict__ neighbor)
{
    __shared__ int s_cnt [NC];
    __shared__ int s_scan[NC];
    __shared__ int s_cur [NC];
    __shared__ int s_cell[4096];

    const int bi  = blockIdx.x;
    const int set = bi >> 2;
    const int b   = bi & 3;
    const float* pts = (set ? neighbor : anchor) + (size_t)b * 4096 * 3;
    const int t = threadIdx.x;

    s_cnt[t] = 0;
    __syncthreads();

#pragma unroll
    for (int r = 0; r < 8; ++r) {
        const int i = t + r * 512;
        const float x = pts[i*3], y = pts[i*3+1], z = pts[i*3+2];
        int cx, cy, cz; cell_coords(x, y, z, cx, cy, cz);
        const int c = cz*64 + cy*8 + cx;
        s_cell[i] = c;
        atomicAdd(&s_cnt[c], 1);
    }
    __syncthreads();

    const int cval = s_cnt[t];
    s_scan[t] = cval;
    __syncthreads();
    for (int off = 1; off < NC; off <<= 1) {
        const int v = (t >= off) ? s_scan[t - off] : 0;
        __syncthreads();
        s_scan[t] += v;
        __syncthreads();
    }
    const int start = s_scan[t] - cval;
    g_cnt  [bi*NC + t] = cval;
    g_start[bi*NC + t] = start;
    s_cur[t] = start;
    __syncthreads();

#pragma unroll
    for (int r = 0; r < 8; ++r) {
        const int i = t + r * 512;
        const int slot = atomicAdd(&s_cur[s_cell[i]], 1);
        g_list[bi*4096 + slot] = i;
    }
}

// ---------------------------------------------------------------------------
// Fused projections. 1024 blocks x 256 threads; blocks [0,512) anchors,
// [512,1024) neighbors; 32 rows per block.
// Phase A: 3->C projections; q stored DUPLICATED as packed (q,q) u64 in smem
// (kills per-cc PACK in phase B); D-path stored directly.
// Phase B: (32 x 128)@(128 x 128), warp = 4 rows, lane = 4 out channels.
// Inner loop per cc: 1 LDG.128 (Wa) + 4 LDS.64 (qq) + 8 FFMA2.
// Output A scaled by log2e (softmax later uses ex2).
// ---------------------------------------------------------------------------
__global__ void __launch_bounds__(256, 4)
proj_kernel(const float* __restrict__ anchor,
            const float* __restrict__ neighbor,
            const float* __restrict__ Wq,
            const float* __restrict__ bq,
            const float* __restrict__ Wk,
            const float* __restrict__ bk,
            const float* __restrict__ Wd,
            const float* __restrict__ bd,
            const float* __restrict__ Wa,
            const float* __restrict__ ba)
{
    constexpr int TR = 32;
    __shared__ unsigned long long q_s2[TR * C];   // packed (q,q)
    __shared__ float p_s[TR * 3];

    const bool AN = blockIdx.x < 512;
    const int  base_row = (AN ? blockIdx.x : blockIdx.x - 512) * TR;
    const float* xyz = AN ? anchor : neighbor;
    const int t = threadIdx.x;

    if (t < TR * 3) p_s[t] = xyz[(size_t)base_row * 3 + t];
    __syncthreads();

    // Phase A: thread (h, c): h = t>>7 handles rows [h*16, h*16+16), channel c.
    {
        const int c = t & 127;
        const int h = t >> 7;
        const float* W1 = AN ? Wq : Wk;
        const float w1x = W1[c], w1y = W1[C + c], w1z = W1[2*C + c];
        const float wdx = Wd[c], wdy = Wd[C + c], wdz = Wd[2*C + c];
        const float qb = AN ? (bq[c] - bk[c]) : 0.0f;
        const float db = AN ? bd[c] : 0.0f;
#pragma unroll
        for (int r = 0; r < 16; ++r) {
            const int rr = h * 16 + r;
            const float x = p_s[rr*3], y = p_s[rr*3+1], z = p_s[rr*3+2];
            const float q = qb + x*w1x + y*w1y + z*w1z;
            unsigned long long qq; PACKF2(qq, q, q);
            q_s2[rr*C + c] = qq;
            const float d = db + x*wdx + y*wdy + z*wdz;
            if (AN) g_AD[(size_t)(base_row + rr) * C + c] = d;
            else    g_KN[(size_t)(base_row + rr) * (2*C) + C + c] = d;
        }
    }
    __syncthreads();

    // Phase B: 8 warps x 4 rows
    const int w = t >> 5, lane = t & 31;
    unsigned long long acc[4][2];
#pragma unroll
    for (int r = 0; r < 4; ++r) { acc[r][0] = 0ull; acc[r][1] = 0ull; }

    const ulonglong2* WaV = (const ulonglong2*)Wa;   // row cc = 32 ulonglong2
    const unsigned long long* qrow = q_s2 + (w * 4) * C;
#pragma unroll 4
    for (int cc = 0; cc < C; ++cc) {
        const ulonglong2 wv = WaV[cc * 32 + lane];
#pragma unroll
        for (int r = 0; r < 4; ++r) {
            const unsigned long long qq = qrow[r * C + cc];
            FFMA2(acc[r][0], qq, wv.x, acc[r][0]);
            FFMA2(acc[r][1], qq, wv.y, acc[r][1]);
        }
    }

    // Epilogue: add bias (anchors), scale by log2e, store.
    const float4 bav = AN ? ((const float4*)ba)[lane]
                          : make_float4(0.f, 0.f, 0.f, 0.f);
#pragma unroll
    for (int r = 0; r < 4; ++r) {
        float a0, a1, a2, a3;
        UNPACKF2(a0, a1, acc[r][0]);
        UNPACKF2(a2, a3, acc[r][1]);
        float4 st;
        st.x = (a0 + bav.x) * LOG2E;
        st.y = (a1 + bav.y) * LOG2E;
        st.z = (a2 + bav.z) * LOG2E;
        st.w = (a3 + bav.w) * LOG2E;
        const int row = base_row + w*4 + r;
        if (AN) ((float4*)(g_QA + (size_t)row * C))[lane] = st;
        else    ((float4*)(g_KN + (size_t)row * (2*C)))[lane] = st;
    }
}

// ---------------------------------------------------------------------------
// Ball query via grid. Warp per anchor (cell-sorted order); 27-cell
// neighborhood = 9 contiguous g_list spans. Collect hits, warp rank-sort.
// ---------------------------------------------------------------------------
__global__ void ballquery_kernel(const float* __restrict__ anchor,
                                 const float* __restrict__ neighbor)
{
    constexpr unsigned FULL = 0xffffffffu;
    constexpr int CAP = 128;
    __shared__ int hbuf[8][CAP];
    __shared__ int sorted[8][KNN];

    const int warp = threadIdx.x >> 5;
    const int lane = threadIdx.x & 31;
    const int p    = blockIdx.x * 8 + warp;
    const int b    = p >> 12;
    const int row  = (b << 12) + g_list[p];

    const float ax = anchor[(size_t)row*3 + 0];
    const float ay = anchor[(size_t)row*3 + 1];
    const float az = anchor[(size_t)row*3 + 2];
    int cx, cy, cz; cell_coords(ax, ay, az, cx, cy, cz);

    const int nbase = (B + b) * NC;
    const int lbase = (B + b) * 4096;
    const float* nb = neighbor + (size_t)b * MPTS * 3;

    const int x0 = max(cx - 1, 0), x1 = min(cx + 1, GC - 1);
    const int z0 = max(cz - 1, 0), z1 = min(cz + 1, GC - 1);
    const int y0 = max(cy - 1, 0), y1 = min(cy + 1, GC - 1);

    int hcnt = 0;
    for (int z = z0; z <= z1; ++z) {
        for (int y = y0; y <= y1; ++y) {
            const int cA = nbase + z*64 + y*8 + x0;
            const int cB = nbase + z*64 + y*8 + x1;
            const int st = g_start[cA];
            const int en = g_start[cB] + g_cnt[cB];
            for (int j = st; j < en; j += 32) {
                const int q = j + lane;
                int m = 0; bool hit = false;
                if (q < en) {
                    m = g_list[lbase + q];
                    const float fx = nb[m*3+0] - ax;
                    const float fy = nb[m*3+1] - ay;
                    const float fz = nb[m*3+2] - az;
                    hit = (fx*fx + fy*fy + fz*fz) < RAD2;
                }
                const unsigned mk = __ballot_sync(FULL, hit);
                if (hit) {
                    const int pos = hcnt + __popc(mk & ((1u << lane) - 1u));
                    if (pos < CAP) hbuf[warp][pos] = m;
                }
                hcnt += __popc(mk);
            }
        }
    }

    __syncwarp(FULL);
    const int n = min(hcnt, CAP);
    const int rounds = (n + 31) >> 5;

    int v[4], rk[4];
#pragma unroll
    for (int r = 0; r < 4; ++r) {
        const int i = lane + 32*r;
        v[r]  = (i < n) ? hbuf[warp][i] : 0x7fffffff;
        rk[r] = 0;
    }
    for (int step = 0; step < 32; ++step) {
#pragma unroll
        for (int s = 0; s < 4; ++s) {
            if (s < rounds) {
                const int u = __shfl_sync(FULL, v[s], step);
#pragma unroll
                for (int r = 0; r < 4; ++r)
                    if (r < rounds) rk[r] += (u < v[r]);
            }
        }
    }
#pragma unroll
    for (int r = 0; r < 4; ++r) {
        const int i = lane + 32*r;
        if (i < n && rk[r] < KNN) sorted[warp][rk[r]] = v[r];
    }
    __syncwarp(FULL);

    const int take  = min(hcnt, KNN);
    const int first = (hcnt > 0) ? sorted[warp][0] : 0;
    g_idx[(size_t)row * KNN + lane] = (lane < take) ? sorted[warp][lane] : first;
}

// ---------------------------------------------------------------------------
// Attention. Warp per anchor (cell-sorted). Lane = 4 channels. QA/KA are
// pre-scaled by log2e, so exp = single ex2.approx. KA'/ND interleaved per
// neighbor row (one gather base). Softmax shift-free (no fp32 overflow:
// |logit*log2e| <= ~94 -> exp2 <= 2e28).
// ---------------------------------------------------------------------------
__global__ void attn_kernel(float* __restrict__ out)
{
    constexpr unsigned FULL = 0xffffffffu;
    const int warp = threadIdx.x >> 5;
    const int lane = threadIdx.x & 31;
    const int p    = blockIdx.x * 8 + warp;
    const int b    = p >> 12;
    const int row  = (b << 12) + g_list[p];

    const float4 qa = ((const float4*)(g_QA + (size_t)row * C))[lane];
    const float4 ad = ((const float4*)(g_AD + (size_t)row * C))[lane];
    const int my_m  = g_idx[(size_t)row * KNN + lane];

    const float* KNb = g_KN + (size_t)b * MPTS * (2*C);

    float4 o = make_float4(-3.4e38f, -3.4e38f, -3.4e38f, -3.4e38f);

#pragma unroll 4
    for (int k = 0; k < KNN; ++k) {
        const int m = __shfl_sync(FULL, my_m, k);
        const float4* base = (const float4*)(KNb + (size_t)m * (2*C));
        const float4 kv = base[lane];
        const float4 nv = base[32 + lane];

        const float e0 = ex2f(qa.x - kv.x);
        const float e1 = ex2f(qa.y - kv.y);
        const float e2 = ex2f(qa.z - kv.z);
        const float e3 = ex2f(qa.w - kv.w);

        float s = (e0 + e1) + (e2 + e3);
#pragma unroll
        for (int off = 16; off; off >>= 1)
            s += __shfl_xor_sync(FULL, s, off);

        const float inv = __fdividef(1.0f, s);
        o.x = fmaxf(o.x, (ad.x - nv.x) * (e0 * inv));
        o.y = fmaxf(o.y, (ad.y - nv.y) * (e1 * inv));
        o.z = fmaxf(o.z, (ad.z - nv.z) * (e2 * inv));
        o.w = fmaxf(o.w, (ad.w - nv.w) * (e3 * inv));
    }

    ((float4*)(out + (size_t)row * C))[lane] = o;
}

// ---------------------------------------------------------------------------
// Launch: fork proj onto a side stream, join before attn.
// ---------------------------------------------------------------------------
extern "C" void kernel_launch(void* const* d_in, const int* in_sizes, int n_in,
                              void* d_out, int out_size)
{
    const float* anchor   = (const float*)d_in[0];
    const float* neighbor = (const float*)d_in[1];
    const float* Wq = (const float*)d_in[2];
    const float* bq = (const float*)d_in[3];
    const float* Wk = (const float*)d_in[4];
    const float* bk = (const float*)d_in[5];
    const float* Wd = (const float*)d_in[6];
    const float* bd = (const float*)d_in[7];
    const float* Wa = (const float*)d_in[8];
    const float* ba = (const float*)d_in[9];
    float* out = (float*)d_out;

    static cudaStream_t s_side = nullptr;
    static cudaEvent_t  e_fork = nullptr, e_join = nullptr;
    if (s_side == nullptr) {
        cudaStreamCreateWithFlags(&s_side, cudaStreamNonBlocking);
        cudaEventCreateWithFlags(&e_fork, cudaEventDisableTiming);
        cudaEventCreateWithFlags(&e_join, cudaEventDisableTiming);
    }

    cudaEventRecord(e_fork, 0);
    cudaStreamWaitEvent(s_side, e_fork, 0);
    proj_kernel<<<1024, 256, 0, s_side>>>(anchor, neighbor,
                                          Wq, bq, Wk, bk, Wd, bd, Wa, ba);
    cudaEventRecord(e_join, s_side);

    gridbuild_kernel<<<8, 512>>>(anchor, neighbor);
    ballquery_kernel<<<2048, 256>>>(anchor, neighbor);

    cudaStreamWaitEvent(0, e_join, 0);
    attn_kernel<<<2048, 256>>>(out);
}

// round 7
// speedup vs baseline: 1.2633x; 1.2633x over previous
#include <cuda_runtime.h>
#include <cuda_bf16.h>

// ---------------------------------------------------------------------------
// Problem constants (fixed shapes)
constexpr int B    = 4;
constexpr int NPTS = 4096;
constexpr int MPTS = 4096;
constexpr int C    = 128;
constexpr int KNN  = 32;
constexpr float RAD2 = 0.12f * 0.12f;
constexpr int GC   = 8;          // grid cells per dim (cell 0.125 > r 0.12)
constexpr int NC   = GC*GC*GC;   // 512 cells per batch
constexpr float LOG2E = 1.4426950408889634f;

// Scratch (__device__ globals; allocation-free rule)
__device__ __align__(16) float g_QA[B*NPTS*C];    // a@(Wq@Wa)+bqa, *log2e
__device__ __align__(16) float g_AD[B*NPTS*C];    // a@Wd + bd
__device__ __align__(16) float g_KN[B*MPTS*2*C];  // row m: [n@(Wk@Wa)*log2e | n@Wd]
__device__ int g_idx[B*NPTS*KNN];

// Precomputed folded weights
__device__ float g_Wqa[3*C];
__device__ float g_Wka[3*C];
__device__ float g_bqa[C];

// Spatial grid: set 0 = anchors, set 1 = neighbors. Index = (set*4+b)*NC + cell.
__device__ int g_cnt  [2*B*NC];
__device__ int g_start[2*B*NC];
__device__ int g_list [2*B*4096];

__device__ __forceinline__ float ex2f(float x) {
    float r; asm("ex2.approx.f32 %0, %1;" : "=f"(r) : "f"(x)); return r;
}

__device__ __forceinline__ void cell_coords(float x, float y, float z,
                                            int& cx, int& cy, int& cz) {
    cx = min(GC-1, max(0, (int)(x * (float)GC)));
    cy = min(GC-1, max(0, (int)(y * (float)GC)));
    cz = min(GC-1, max(0, (int)(z * (float)GC)));
}

// ---------------------------------------------------------------------------
// Weight folding: Wqa = (Wq@Wa)*log2e, Wka = (Wk@Wa)*log2e,
// bqa = ((bq-bk)@Wa + ba)*log2e. One block, 128 threads (thread = out channel).
// ---------------------------------------------------------------------------
__global__ void precompute_kernel(const float* __restrict__ Wq,
                                  const float* __restrict__ bq,
                                  const float* __restrict__ Wk,
                                  const float* __restrict__ bk,
                                  const float* __restrict__ Wa,
                                  const float* __restrict__ ba)
{
    __shared__ float s_wq[3*C], s_wk[3*C], s_bqk[C];
    const int c = threadIdx.x;
    for (int i = c; i < 3*C; i += C) { s_wq[i] = Wq[i]; s_wk[i] = Wk[i]; }
    s_bqk[c] = bq[c] - bk[c];
    __syncthreads();

    float aq0=0.f, aq1=0.f, aq2=0.f, ak0=0.f, ak1=0.f, ak2=0.f, ab=0.f;
#pragma unroll 8
    for (int k = 0; k < C; ++k) {
        const float w = Wa[k*C + c];            // coalesced
        aq0 += s_wq[k      ] * w;
        aq1 += s_wq[C   + k] * w;
        aq2 += s_wq[2*C + k] * w;
        ak0 += s_wk[k      ] * w;
        ak1 += s_wk[C   + k] * w;
        ak2 += s_wk[2*C + k] * w;
        ab  += s_bqk[k] * w;
    }
    g_Wqa[c] = aq0*LOG2E; g_Wqa[C + c] = aq1*LOG2E; g_Wqa[2*C + c] = aq2*LOG2E;
    g_Wka[c] = ak0*LOG2E; g_Wka[C + c] = ak1*LOG2E; g_Wka[2*C + c] = ak2*LOG2E;
    g_bqa[c] = (ab + ba[c]) * LOG2E;
}

// ---------------------------------------------------------------------------
// Streaming projections: blocks [0,512) anchors, [512,1024) neighbors,
// 32 rows per block, 256 threads (half-block h handles rows [h*16,h*16+16),
// thread channel c = t&127). Per (row,channel): 6 FMA + 2 coalesced stores.
// ---------------------------------------------------------------------------
__global__ void __launch_bounds__(256)
proj_kernel(const float* __restrict__ anchor,
            const float* __restrict__ neighbor,
            const float* __restrict__ Wd,
            const float* __restrict__ bd)
{
    constexpr int TR = 32;
    __shared__ float p_s[TR * 3];

    const bool AN = blockIdx.x < 512;
    const int  base_row = (AN ? blockIdx.x : blockIdx.x - 512) * TR;
    const float* xyz = AN ? anchor : neighbor;
    const int t = threadIdx.x;

    if (t < TR * 3) p_s[t] = xyz[(size_t)base_row * 3 + t];
    __syncthreads();

    const int c = t & 127;
    const int h = t >> 7;
    const float* WA = AN ? g_Wqa : g_Wka;
    const float wax = WA[c], way = WA[C + c], waz = WA[2*C + c];
    const float wdx = Wd[c], wdy = Wd[C + c], wdz = Wd[2*C + c];
    const float ab = AN ? g_bqa[c] : 0.0f;
    const float db = AN ? bd[c]    : 0.0f;

#pragma unroll
    for (int r = 0; r < 16; ++r) {
        const int rr = h * 16 + r;
        const float x = p_s[rr*3], y = p_s[rr*3+1], z = p_s[rr*3+2];
        const float a = ab + x*wax + y*way + z*waz;
        const float d = db + x*wdx + y*wdy + z*wdz;
        const int row = base_row + rr;
        if (AN) {
            g_QA[(size_t)row * C + c] = a;
            g_AD[(size_t)row * C + c] = d;
        } else {
            g_KN[(size_t)row * (2*C) + c]     = a;
            g_KN[(size_t)row * (2*C) + C + c] = d;
        }
    }
}

// ---------------------------------------------------------------------------
// Fused grid build: one block per (set, batch). 512 threads, 4096 points.
// ---------------------------------------------------------------------------
__global__ void gridbuild_kernel(const float* __restrict__ anchor,
                                 const float* __restrict__ neighbor)
{
    __shared__ int s_cnt [NC];
    __shared__ int s_scan[NC];
    __shared__ int s_cur [NC];
    __shared__ int s_cell[4096];

    const int bi  = blockIdx.x;
    const int set = bi >> 2;
    const int b   = bi & 3;
    const float* pts = (set ? neighbor : anchor) + (size_t)b * 4096 * 3;
    const int t = threadIdx.x;

    s_cnt[t] = 0;
    __syncthreads();

#pragma unroll
    for (int r = 0; r < 8; ++r) {
        const int i = t + r * 512;
        const float x = pts[i*3], y = pts[i*3+1], z = pts[i*3+2];
        int cx, cy, cz; cell_coords(x, y, z, cx, cy, cz);
        const int c = cz*64 + cy*8 + cx;
        s_cell[i] = c;
        atomicAdd(&s_cnt[c], 1);
    }
    __syncthreads();

    const int cval = s_cnt[t];
    s_scan[t] = cval;
    __syncthreads();
    for (int off = 1; off < NC; off <<= 1) {
        const int v = (t >= off) ? s_scan[t - off] : 0;
        __syncthreads();
        s_scan[t] += v;
        __syncthreads();
    }
    const int start = s_scan[t] - cval;
    g_cnt  [bi*NC + t] = cval;
    g_start[bi*NC + t] = start;
    s_cur[t] = start;
    __syncthreads();

#pragma unroll
    for (int r = 0; r < 8; ++r) {
        const int i = t + r * 512;
        const int slot = atomicAdd(&s_cur[s_cell[i]], 1);
        g_list[bi*4096 + slot] = i;
    }
}

// ---------------------------------------------------------------------------
// Ball query via grid. Warp per anchor (cell-sorted order); 27-cell
// neighborhood = 9 contiguous g_list spans. Collect hits, warp rank-sort.
// ---------------------------------------------------------------------------
__global__ void ballquery_kernel(const float* __restrict__ anchor,
                                 const float* __restrict__ neighbor)
{
    constexpr unsigned FULL = 0xffffffffu;
    constexpr int CAP = 128;
    __shared__ int hbuf[8][CAP];
    __shared__ int sorted[8][KNN];

    const int warp = threadIdx.x >> 5;
    const int lane = threadIdx.x & 31;
    const int p    = blockIdx.x * 8 + warp;
    const int b    = p >> 12;
    const int row  = (b << 12) + g_list[p];

    const float ax = anchor[(size_t)row*3 + 0];
    const float ay = anchor[(size_t)row*3 + 1];
    const float az = anchor[(size_t)row*3 + 2];
    int cx, cy, cz; cell_coords(ax, ay, az, cx, cy, cz);

    const int nbase = (B + b) * NC;
    const int lbase = (B + b) * 4096;
    const float* nb = neighbor + (size_t)b * MPTS * 3;

    const int x0 = max(cx - 1, 0), x1 = min(cx + 1, GC - 1);
    const int z0 = max(cz - 1, 0), z1 = min(cz + 1, GC - 1);
    const int y0 = max(cy - 1, 0), y1 = min(cy + 1, GC - 1);

    int hcnt = 0;
    for (int z = z0; z <= z1; ++z) {
        for (int y = y0; y <= y1; ++y) {
            const int cA = nbase + z*64 + y*8 + x0;
            const int cB = nbase + z*64 + y*8 + x1;
            const int st = g_start[cA];
            const int en = g_start[cB] + g_cnt[cB];
            for (int j = st; j < en; j += 32) {
                const int q = j + lane;
                int m = 0; bool hit = false;
                if (q < en) {
                    m = g_list[lbase + q];
                    const float fx = nb[m*3+0] - ax;
                    const float fy = nb[m*3+1] - ay;
                    const float fz = nb[m*3+2] - az;
                    hit = (fx*fx + fy*fy + fz*fz) < RAD2;
                }
                const unsigned mk = __ballot_sync(FULL, hit);
                if (hit) {
                    const int pos = hcnt + __popc(mk & ((1u << lane) - 1u));
                    if (pos < CAP) hbuf[warp][pos] = m;
                }
                hcnt += __popc(mk);
            }
        }
    }

    __syncwarp(FULL);
    const int n = min(hcnt, CAP);
    const int rounds = (n + 31) >> 5;

    int v[4], rk[4];
#pragma unroll
    for (int r = 0; r < 4; ++r) {
        const int i = lane + 32*r;
        v[r]  = (i < n) ? hbuf[warp][i] : 0x7fffffff;
        rk[r] = 0;
    }
    for (int step = 0; step < 32; ++step) {
#pragma unroll
        for (int s = 0; s < 4; ++s) {
            if (s < rounds) {
                const int u = __shfl_sync(FULL, v[s], step);
#pragma unroll
                for (int r = 0; r < 4; ++r)
                    if (r < rounds) rk[r] += (u < v[r]);
            }
        }
    }
#pragma unroll
    for (int r = 0; r < 4; ++r) {
        const int i = lane + 32*r;
        if (i < n && rk[r] < KNN) sorted[warp][rk[r]] = v[r];
    }
    __syncwarp(FULL);

    const int take  = min(hcnt, KNN);
    const int first = (hcnt > 0) ? sorted[warp][0] : 0;
    g_idx[(size_t)row * KNN + lane] = (lane < take) ? sorted[warp][lane] : first;
}

// ---------------------------------------------------------------------------
// Attention. Warp per anchor (cell-sorted). Lane = 4 channels. QA/KA are
// pre-scaled by log2e, so exp = single ex2.approx. KA'/ND interleaved per
// neighbor row (one gather base). Softmax shift-free (no fp32 overflow).
// ---------------------------------------------------------------------------
__global__ void attn_kernel(float* __restrict__ out)
{
    constexpr unsigned FULL = 0xffffffffu;
    const int warp = threadIdx.x >> 5;
    const int lane = threadIdx.x & 31;
    const int p    = blockIdx.x * 8 + warp;
    const int b    = p >> 12;
    const int row  = (b << 12) + g_list[p];

    const float4 qa = ((const float4*)(g_QA + (size_t)row * C))[lane];
    const float4 ad = ((const float4*)(g_AD + (size_t)row * C))[lane];
    const int my_m  = g_idx[(size_t)row * KNN + lane];

    const float* KNb = g_KN + (size_t)b * MPTS * (2*C);

    float4 o = make_float4(-3.4e38f, -3.4e38f, -3.4e38f, -3.4e38f);

#pragma unroll 4
    for (int k = 0; k < KNN; ++k) {
        const int m = __shfl_sync(FULL, my_m, k);
        const float4* base = (const float4*)(KNb + (size_t)m * (2*C));
        const float4 kv = base[lane];
        const float4 nv = base[32 + lane];

        const float e0 = ex2f(qa.x - kv.x);
        const float e1 = ex2f(qa.y - kv.y);
        const float e2 = ex2f(qa.z - kv.z);
        const float e3 = ex2f(qa.w - kv.w);

        float s = (e0 + e1) + (e2 + e3);
#pragma unroll
        for (int off = 16; off; off >>= 1)
            s += __shfl_xor_sync(FULL, s, off);

        const float inv = __fdividef(1.0f, s);
        o.x = fmaxf(o.x, (ad.x - nv.x) * (e0 * inv));
        o.y = fmaxf(o.y, (ad.y - nv.y) * (e1 * inv));
        o.z = fmaxf(o.z, (ad.z - nv.z) * (e2 * inv));
        o.w = fmaxf(o.w, (ad.w - nv.w) * (e3 * inv));
    }

    ((float4*)(out + (size_t)row * C))[lane] = o;
}

// ---------------------------------------------------------------------------
// Launch: side stream = precompute -> proj; main = gridbuild -> ballquery.
// Join before attn.
// ---------------------------------------------------------------------------
extern "C" void kernel_launch(void* const* d_in, const int* in_sizes, int n_in,
                              void* d_out, int out_size)
{
    const float* anchor   = (const float*)d_in[0];
    const float* neighbor = (const float*)d_in[1];
    const float* Wq = (const float*)d_in[2];
    const float* bq = (const float*)d_in[3];
    const float* Wk = (const float*)d_in[4];
    const float* bk = (const float*)d_in[5];
    const float* Wd = (const float*)d_in[6];
    const float* bd = (const float*)d_in[7];
    const float* Wa = (const float*)d_in[8];
    const float* ba = (const float*)d_in[9];
    float* out = (float*)d_out;

    static cudaStream_t s_side = nullptr;
    static cudaEvent_t  e_fork = nullptr, e_join = nullptr;
    if (s_side == nullptr) {
        cudaStreamCreateWithFlags(&s_side, cudaStreamNonBlocking);
        cudaEventCreateWithFlags(&e_fork, cudaEventDisableTiming);
        cudaEventCreateWithFlags(&e_join, cudaEventDisableTiming);
    }

    cudaEventRecord(e_fork, 0);
    cudaStreamWaitEvent(s_side, e_fork, 0);
    precompute_kernel<<<1, 128, 0, s_side>>>(Wq, bq, Wk, bk, Wa, ba);
    proj_kernel<<<1024, 256, 0, s_side>>>(anchor, neighbor, Wd, bd);
    cudaEventRecord(e_join, s_side);

    gridbuild_kernel<<<8, 512>>>(anchor, neighbor);
    ballquery_kernel<<<2048, 256>>>(anchor, neighbor);

    cudaStreamWaitEvent(0, e_join, 0);
    attn_kernel<<<2048, 256>>>(out);
}

// round 8
// speedup vs baseline: 1.4250x; 1.1279x over previous
#include <cuda_runtime.h>
#include <cuda_bf16.h>

// ---------------------------------------------------------------------------
// Problem constants (fixed shapes)
constexpr int B    = 4;
constexpr int NPTS = 4096;
constexpr int MPTS = 4096;
constexpr int C    = 128;
constexpr int KNN  = 32;
constexpr float RAD2 = 0.12f * 0.12f;
constexpr int GC   = 8;          // grid cells per dim (cell 0.125 > r 0.12)
constexpr int NC   = GC*GC*GC;   // 512 cells per batch
constexpr float LOG2E = 1.4426950408889634f;

// Scratch (__device__ globals; allocation-free rule)
__device__ __align__(16) float g_QA[B*NPTS*C];    // a@(Wq@Wa)+bqa, *log2e
__device__ __align__(16) float g_AD[B*NPTS*C];    // a@Wd + bd
__device__ __align__(16) float g_KN[B*MPTS*2*C];  // row m: [n@(Wk@Wa)*log2e | n@Wd]

// Precomputed folded weights
__device__ float g_Wqa[3*C];
__device__ float g_Wka[3*C];
__device__ float g_bqa[C];

// Spatial grid: set 0 = anchors, set 1 = neighbors. Index = (set*4+b)*NC + cell.
__device__ int    g_cnt  [2*B*NC];
__device__ int    g_start[2*B*NC];
__device__ __align__(16) float4 g_pts[2*B*4096];  // cell-sorted (x,y,z,idx)

__device__ __forceinline__ float ex2f(float x) {
    float r; asm("ex2.approx.f32 %0, %1;" : "=f"(r) : "f"(x)); return r;
}
__device__ __forceinline__ int redux_min_s32(int v) {
    int r; asm("redux.sync.min.s32 %0, %1, 0xffffffff;" : "=r"(r) : "r"(v));
    return r;
}

__device__ __forceinline__ void cell_coords(float x, float y, float z,
                                            int& cx, int& cy, int& cz) {
    cx = min(GC-1, max(0, (int)(x * (float)GC)));
    cy = min(GC-1, max(0, (int)(y * (float)GC)));
    cz = min(GC-1, max(0, (int)(z * (float)GC)));
}

// ---------------------------------------------------------------------------
// Weight folding: Wqa = (Wq@Wa)*log2e, Wka = (Wk@Wa)*log2e,
// bqa = ((bq-bk)@Wa + ba)*log2e. One block, 128 threads (thread = out channel).
// ---------------------------------------------------------------------------
__global__ void precompute_kernel(const float* __restrict__ Wq,
                                  const float* __restrict__ bq,
                                  const float* __restrict__ Wk,
                                  const float* __restrict__ bk,
                                  const float* __restrict__ Wa,
                                  const float* __restrict__ ba)
{
    __shared__ float s_wq[3*C], s_wk[3*C], s_bqk[C];
    const int c = threadIdx.x;
    for (int i = c; i < 3*C; i += C) { s_wq[i] = Wq[i]; s_wk[i] = Wk[i]; }
    s_bqk[c] = bq[c] - bk[c];
    __syncthreads();

    float aq0=0.f, aq1=0.f, aq2=0.f, ak0=0.f, ak1=0.f, ak2=0.f, ab=0.f;
#pragma unroll 8
    for (int k = 0; k < C; ++k) {
        const float w = Wa[k*C + c];            // coalesced
        aq0 += s_wq[k      ] * w;
        aq1 += s_wq[C   + k] * w;
        aq2 += s_wq[2*C + k] * w;
        ak0 += s_wk[k      ] * w;
        ak1 += s_wk[C   + k] * w;
        ak2 += s_wk[2*C + k] * w;
        ab  += s_bqk[k] * w;
    }
    g_Wqa[c] = aq0*LOG2E; g_Wqa[C + c] = aq1*LOG2E; g_Wqa[2*C + c] = aq2*LOG2E;
    g_Wka[c] = ak0*LOG2E; g_Wka[C + c] = ak1*LOG2E; g_Wka[2*C + c] = ak2*LOG2E;
    g_bqa[c] = (ab + ba[c]) * LOG2E;
}

// ---------------------------------------------------------------------------
// Streaming projections: blocks [0,512) anchors, [512,1024) neighbors,
// 32 rows per block, 256 threads. Per (row,channel): 6 FMA + 2 stores.
// ---------------------------------------------------------------------------
__global__ void __launch_bounds__(256)
proj_kernel(const float* __restrict__ anchor,
            const float* __restrict__ neighbor,
            const float* __restrict__ Wd,
            const float* __restrict__ bd)
{
    constexpr int TR = 32;
    __shared__ float p_s[TR * 3];

    const bool AN = blockIdx.x < 512;
    const int  base_row = (AN ? blockIdx.x : blockIdx.x - 512) * TR;
    const float* xyz = AN ? anchor : neighbor;
    const int t = threadIdx.x;

    if (t < TR * 3) p_s[t] = xyz[(size_t)base_row * 3 + t];
    __syncthreads();

    const int c = t & 127;
    const int h = t >> 7;
    const float* WA = AN ? g_Wqa : g_Wka;
    const float wax = WA[c], way = WA[C + c], waz = WA[2*C + c];
    const float wdx = Wd[c], wdy = Wd[C + c], wdz = Wd[2*C + c];
    const float ab = AN ? g_bqa[c] : 0.0f;
    const float db = AN ? bd[c]    : 0.0f;

#pragma unroll
    for (int r = 0; r < 16; ++r) {
        const int rr = h * 16 + r;
        const float x = p_s[rr*3], y = p_s[rr*3+1], z = p_s[rr*3+2];
        const float a = ab + x*wax + y*way + z*waz;
        const float d = db + x*wdx + y*wdy + z*wdz;
        const int row = base_row + rr;
        if (AN) {
            g_QA[(size_t)row * C + c] = a;
            g_AD[(size_t)row * C + c] = d;
        } else {
            g_KN[(size_t)row * (2*C) + c]     = a;
            g_KN[(size_t)row * (2*C) + C + c] = d;
        }
    }
}

// ---------------------------------------------------------------------------
// Fused grid build: one block per (set, batch). 512 threads, 4096 points.
// Also emits g_pts: cell-sorted float4(x, y, z, local_idx) for coalesced
// candidate loads downstream.
// ---------------------------------------------------------------------------
__global__ void gridbuild_kernel(const float* __restrict__ anchor,
                                 const float* __restrict__ neighbor)
{
    __shared__ int s_cnt [NC];
    __shared__ int s_scan[NC];
    __shared__ int s_cur [NC];
    __shared__ int s_cell[4096];

    const int bi  = blockIdx.x;
    const int set = bi >> 2;
    const int b   = bi & 3;
    const float* pts = (set ? neighbor : anchor) + (size_t)b * 4096 * 3;
    const int t = threadIdx.x;

    s_cnt[t] = 0;
    __syncthreads();

#pragma unroll
    for (int r = 0; r < 8; ++r) {
        const int i = t + r * 512;
        const float x = pts[i*3], y = pts[i*3+1], z = pts[i*3+2];
        int cx, cy, cz; cell_coords(x, y, z, cx, cy, cz);
        const int c = cz*64 + cy*8 + cx;
        s_cell[i] = c;
        atomicAdd(&s_cnt[c], 1);
    }
    __syncthreads();

    const int cval = s_cnt[t];
    s_scan[t] = cval;
    __syncthreads();
    for (int off = 1; off < NC; off <<= 1) {
        const int v = (t >= off) ? s_scan[t - off] : 0;
        __syncthreads();
        s_scan[t] += v;
        __syncthreads();
    }
    const int start = s_scan[t] - cval;
    g_cnt  [bi*NC + t] = cval;
    g_start[bi*NC + t] = start;
    s_cur[t] = start;
    __syncthreads();

#pragma unroll
    for (int r = 0; r < 8; ++r) {
        const int i = t + r * 512;
        const float x = pts[i*3], y = pts[i*3+1], z = pts[i*3+2];  // L1 hit
        const int slot = atomicAdd(&s_cur[s_cell[i]], 1);
        g_pts[bi*4096 + slot] = make_float4(x, y, z, __int_as_float(i));
    }
}

// ---------------------------------------------------------------------------
// Merged ball query + attention. Warp per anchor (cell-sorted order).
// Phase 1: scan 9 contiguous spans of g_pts (coalesced float4 loads), collect
//          hits into smem.
// Phase 2: slot selection. Fast path (hcnt <= 32): raw hit set + min-index
//          padding (softmax/max are permutation-invariant, only the SET of
//          first-K-by-index matters). Slow path: warp rank-sort.
// Phase 3: attention (ex2, shift-free softmax, max over k).
// ---------------------------------------------------------------------------
__global__ void __launch_bounds__(256)
ballattn_kernel(float* __restrict__ out)
{
    constexpr unsigned FULL = 0xffffffffu;
    constexpr int CAP = 128;
    __shared__ int hbuf[8][CAP];
    __shared__ int sorted[8][KNN];

    const int warp = threadIdx.x >> 5;
    const int lane = threadIdx.x & 31;
    const int p    = blockIdx.x * 8 + warp;      // cell-sorted anchor position
    const int b    = p >> 12;

    const float4 a4 = g_pts[p];                  // anchor set region
    const float ax = a4.x, ay = a4.y, az = a4.z;
    const int row  = (b << 12) + __float_as_int(a4.w);
    int cx, cy, cz; cell_coords(ax, ay, az, cx, cy, cz);

    const int nbase = (B + b) * NC;              // neighbor grid region
    const float4* cand = g_pts + (B + b) * 4096; // neighbor pts region

    const int x0 = max(cx - 1, 0), x1 = min(cx + 1, GC - 1);
    const int z0 = max(cz - 1, 0), z1 = min(cz + 1, GC - 1);
    const int y0 = max(cy - 1, 0), y1 = min(cy + 1, GC - 1);

    // --- Phase 1: collect hits ---
    int hcnt = 0;
    for (int z = z0; z <= z1; ++z) {
        for (int y = y0; y <= y1; ++y) {
            const int cA = nbase + z*64 + y*8 + x0;
            const int cB = nbase + z*64 + y*8 + x1;
            const int st = g_start[cA];
            const int en = g_start[cB] + g_cnt[cB];
            for (int j = st; j < en; j += 32) {
                const int q = j + lane;
                int m = 0; bool hit = false;
                if (q < en) {
                    const float4 c4 = cand[q];   // coalesced LDG.128
                    const float fx = c4.x - ax;
                    const float fy = c4.y - ay;
                    const float fz = c4.z - az;
                    hit = (fx*fx + fy*fy + fz*fz) < RAD2;
                    m = __float_as_int(c4.w);
                }
                const unsigned mk = __ballot_sync(FULL, hit);
                if (hit) {
                    const int pos = hcnt + __popc(mk & ((1u << lane) - 1u));
                    if (pos < CAP) hbuf[warp][pos] = m;
                }
                hcnt += __popc(mk);
            }
        }
    }
    __syncwarp(FULL);

    // --- Phase 2: slot selection ---
    int my_m;
    if (hcnt <= KNN) {
        const int v = (lane < hcnt) ? hbuf[warp][lane] : 0x7fffffff;
        const int mn = redux_min_s32(v);         // smallest original index
        my_m = (lane < hcnt) ? v : ((hcnt > 0) ? mn : 0);
    } else {
        const int n = min(hcnt, CAP);
        const int rounds = (n + 31) >> 5;
        int v[4], rk[4];
#pragma unroll
        for (int r = 0; r < 4; ++r) {
            const int i = lane + 32*r;
            v[r]  = (i < n) ? hbuf[warp][i] : 0x7fffffff;
            rk[r] = 0;
        }
        for (int step = 0; step < 32; ++step) {
#pragma unroll
            for (int s = 0; s < 4; ++s) {
                if (s < rounds) {
                    const int u = __shfl_sync(FULL, v[s], step);
#pragma unroll
                    for (int r = 0; r < 4; ++r)
                        if (r < rounds) rk[r] += (u < v[r]);
                }
            }
        }
#pragma unroll
        for (int r = 0; r < 4; ++r) {
            const int i = lane + 32*r;
            if (i < n && rk[r] < KNN) sorted[warp][rk[r]] = v[r];
        }
        __syncwarp(FULL);
        my_m = sorted[warp][lane];
    }

    // --- Phase 3: attention ---
    const float4 qa = ((const float4*)(g_QA + (size_t)row * C))[lane];
    const float4 ad = ((const float4*)(g_AD + (size_t)row * C))[lane];
    const float* KNb = g_KN + (size_t)b * MPTS * (2*C);

    float4 o = make_float4(-3.4e38f, -3.4e38f, -3.4e38f, -3.4e38f);

#pragma unroll 4
    for (int k = 0; k < KNN; ++k) {
        const int m = __shfl_sync(FULL, my_m, k);
        const float4* base = (const float4*)(KNb + (size_t)m * (2*C));
        const float4 kv = base[lane];
        const float4 nv = base[32 + lane];

        const float e0 = ex2f(qa.x - kv.x);
        const float e1 = ex2f(qa.y - kv.y);
        const float e2 = ex2f(qa.z - kv.z);
        const float e3 = ex2f(qa.w - kv.w);

        float s = (e0 + e1) + (e2 + e3);
#pragma unroll
        for (int off = 16; off; off >>= 1)
            s += __shfl_xor_sync(FULL, s, off);

        const float inv = __fdividef(1.0f, s);
        o.x = fmaxf(o.x, (ad.x - nv.x) * (e0 * inv));
        o.y = fmaxf(o.y, (ad.y - nv.y) * (e1 * inv));
        o.z = fmaxf(o.z, (ad.z - nv.z) * (e2 * inv));
        o.w = fmaxf(o.w, (ad.w - nv.w) * (e3 * inv));
    }

    ((float4*)(out + (size_t)row * C))[lane] = o;
}

// ---------------------------------------------------------------------------
// Launch: side = precompute -> proj; main = gridbuild. Join -> merged kernel.
// ---------------------------------------------------------------------------
extern "C" void kernel_launch(void* const* d_in, const int* in_sizes, int n_in,
                              void* d_out, int out_size)
{
    const float* anchor   = (const float*)d_in[0];
    const float* neighbor = (const float*)d_in[1];
    const float* Wq = (const float*)d_in[2];
    const float* bq = (const float*)d_in[3];
    const float* Wk = (const float*)d_in[4];
    const float* bk = (const float*)d_in[5];
    const float* Wd = (const float*)d_in[6];
    const float* bd = (const float*)d_in[7];
    const float* Wa = (const float*)d_in[8];
    const float* ba = (const float*)d_in[9];
    float* out = (float*)d_out;

    static cudaStream_t s_side = nullptr;
    static cudaEvent_t  e_fork = nullptr, e_join = nullptr;
    if (s_side == nullptr) {
        cudaStreamCreateWithFlags(&s_side, cudaStreamNonBlocking);
        cudaEventCreateWithFlags(&e_fork, cudaEventDisableTiming);
        cudaEventCreateWithFlags(&e_join, cudaEventDisableTiming);
    }

    cudaEventRecord(e_fork, 0);
    cudaStreamWaitEvent(s_side, e_fork, 0);
    precompute_kernel<<<1, 128, 0, s_side>>>(Wq, bq, Wk, bk, Wa, ba);
    proj_kernel<<<1024, 256, 0, s_side>>>(anchor, neighbor, Wd, bd);
    cudaEventRecord(e_join, s_side);

    gridbuild_kernel<<<8, 512>>>(anchor, neighbor);

    cudaStreamWaitEvent(0, e_join, 0);
    ballattn_kernel<<<2048, 256>>>(out);
}

// round 9
// speedup vs baseline: 1.5469x; 1.0856x over previous
#include <cuda_runtime.h>
#include <cuda_bf16.h>

// ---------------------------------------------------------------------------
// Problem constants (fixed shapes)
constexpr int B    = 4;
constexpr int NPTS = 4096;
constexpr int MPTS = 4096;
constexpr int C    = 128;
constexpr int KNN  = 32;
constexpr float RAD2 = 0.12f * 0.12f;
constexpr int GC   = 8;          // grid cells per dim (cell 0.125 > r 0.12)
constexpr int NC   = GC*GC*GC;   // 512 cells per batch
constexpr float LOG2E = 1.4426950408889634f;

// Scratch (__device__ globals; allocation-free rule)
__device__ __align__(16) float g_QA[B*NPTS*C];    // (a@(Wq@Wa)+bqa)*log2e
__device__ __align__(16) float g_AD[B*NPTS*C];    // a@Wd + bd
__device__ __align__(16) float g_KN[B*MPTS*2*C];  // row m: [exp2(-ka*log2e) | n@Wd]

// Precomputed folded weights
__device__ float g_Wqa[3*C];
__device__ float g_Wka[3*C];
__device__ float g_bqa[C];

// Spatial grid: set 0 = anchors, set 1 = neighbors. Index = (set*4+b)*NC + cell.
__device__ int    g_cnt  [2*B*NC];
__device__ int    g_start[2*B*NC];
__device__ __align__(16) float4 g_pts[2*B*4096];  // cell-sorted (x,y,z,idx)

__device__ __forceinline__ float ex2f(float x) {
    float r; asm("ex2.approx.f32 %0, %1;" : "=f"(r) : "f"(x)); return r;
}
__device__ __forceinline__ int redux_min_s32(int v) {
    int r; asm("redux.sync.min.s32 %0, %1, 0xffffffff;" : "=r"(r) : "r"(v));
    return r;
}

__device__ __forceinline__ void cell_coords(float x, float y, float z,
                                            int& cx, int& cy, int& cz) {
    cx = min(GC-1, max(0, (int)(x * (float)GC)));
    cy = min(GC-1, max(0, (int)(y * (float)GC)));
    cz = min(GC-1, max(0, (int)(z * (float)GC)));
}

// ---------------------------------------------------------------------------
// Weight folding: Wqa = (Wq@Wa)*log2e, Wka = (Wk@Wa)*log2e,
// bqa = ((bq-bk)@Wa + ba)*log2e. One block, 128 threads (thread = out channel).
// ---------------------------------------------------------------------------
__global__ void precompute_kernel(const float* __restrict__ Wq,
                                  const float* __restrict__ bq,
                                  const float* __restrict__ Wk,
                                  const float* __restrict__ bk,
                                  const float* __restrict__ Wa,
                                  const float* __restrict__ ba)
{
    __shared__ float s_wq[3*C], s_wk[3*C], s_bqk[C];
    const int c = threadIdx.x;
    for (int i = c; i < 3*C; i += C) { s_wq[i] = Wq[i]; s_wk[i] = Wk[i]; }
    s_bqk[c] = bq[c] - bk[c];
    __syncthreads();

    float aq0=0.f, aq1=0.f, aq2=0.f, ak0=0.f, ak1=0.f, ak2=0.f, ab=0.f;
#pragma unroll 8
    for (int k = 0; k < C; ++k) {
        const float w = Wa[k*C + c];            // coalesced
        aq0 += s_wq[k      ] * w;
        aq1 += s_wq[C   + k] * w;
        aq2 += s_wq[2*C + k] * w;
        ak0 += s_wk[k      ] * w;
        ak1 += s_wk[C   + k] * w;
        ak2 += s_wk[2*C + k] * w;
        ab  += s_bqk[k] * w;
    }
    g_Wqa[c] = aq0*LOG2E; g_Wqa[C + c] = aq1*LOG2E; g_Wqa[2*C + c] = aq2*LOG2E;
    g_Wka[c] = ak0*LOG2E; g_Wka[C + c] = ak1*LOG2E; g_Wka[2*C + c] = ak2*LOG2E;
    g_bqa[c] = (ab + ba[c]) * LOG2E;
}

// ---------------------------------------------------------------------------
// Streaming projections: blocks [0,512) anchors, [512,1024) neighbors,
// 32 rows per block, 256 threads. Neighbor A-path is stored as
// EK = exp2(-ka*log2e)  (exp factored out of the attention inner loop).
// ---------------------------------------------------------------------------
__global__ void __launch_bounds__(256)
proj_kernel(const float* __restrict__ anchor,
            const float* __restrict__ neighbor,
            const float* __restrict__ Wd,
            const float* __restrict__ bd)
{
    constexpr int TR = 32;
    __shared__ float p_s[TR * 3];

    const bool AN = blockIdx.x < 512;
    const int  base_row = (AN ? blockIdx.x : blockIdx.x - 512) * TR;
    const float* xyz = AN ? anchor : neighbor;
    const int t = threadIdx.x;

    if (t < TR * 3) p_s[t] = xyz[(size_t)base_row * 3 + t];
    __syncthreads();

    const int c = t & 127;
    const int h = t >> 7;
    const float* WA = AN ? g_Wqa : g_Wka;
    const float wax = WA[c], way = WA[C + c], waz = WA[2*C + c];
    const float wdx = Wd[c], wdy = Wd[C + c], wdz = Wd[2*C + c];
    const float ab = AN ? g_bqa[c] : 0.0f;
    const float db = AN ? bd[c]    : 0.0f;

#pragma unroll
    for (int r = 0; r < 16; ++r) {
        const int rr = h * 16 + r;
        const float x = p_s[rr*3], y = p_s[rr*3+1], z = p_s[rr*3+2];
        const float a = ab + x*wax + y*way + z*waz;
        const float d = db + x*wdx + y*wdy + z*wdz;
        const int row = base_row + rr;
        if (AN) {
            g_QA[(size_t)row * C + c] = a;
            g_AD[(size_t)row * C + c] = d;
        } else {
            g_KN[(size_t)row * (2*C) + c]     = ex2f(-a);   // EK factor
            g_KN[(size_t)row * (2*C) + C + c] = d;
        }
    }
}

// ---------------------------------------------------------------------------
// Fused grid build: one block per (set, batch). 512 threads, 4096 points.
// Emits g_pts: cell-sorted float4(x, y, z, local_idx).
// ---------------------------------------------------------------------------
__global__ void gridbuild_kernel(const float* __restrict__ anchor,
                                 const float* __restrict__ neighbor)
{
    __shared__ int s_cnt [NC];
    __shared__ int s_scan[NC];
    __shared__ int s_cur [NC];
    __shared__ int s_cell[4096];

    const int bi  = blockIdx.x;
    const int set = bi >> 2;
    const int b   = bi & 3;
    const float* pts = (set ? neighbor : anchor) + (size_t)b * 4096 * 3;
    const int t = threadIdx.x;

    s_cnt[t] = 0;
    __syncthreads();

#pragma unroll
    for (int r = 0; r < 8; ++r) {
        const int i = t + r * 512;
        const float x = pts[i*3], y = pts[i*3+1], z = pts[i*3+2];
        int cx, cy, cz; cell_coords(x, y, z, cx, cy, cz);
        const int c = cz*64 + cy*8 + cx;
        s_cell[i] = c;
        atomicAdd(&s_cnt[c], 1);
    }
    __syncthreads();

    const int cval = s_cnt[t];
    s_scan[t] = cval;
    __syncthreads();
    for (int off = 1; off < NC; off <<= 1) {
        const int v = (t >= off) ? s_scan[t - off] : 0;
        __syncthreads();
        s_scan[t] += v;
        __syncthreads();
    }
    const int start = s_scan[t] - cval;
    g_cnt  [bi*NC + t] = cval;
    g_start[bi*NC + t] = start;
    s_cur[t] = start;
    __syncthreads();

#pragma unroll
    for (int r = 0; r < 8; ++r) {
        const int i = t + r * 512;
        const float x = pts[i*3], y = pts[i*3+1], z = pts[i*3+2];  // L1 hit
        const int slot = atomicAdd(&s_cur[s_cell[i]], 1);
        g_pts[bi*4096 + slot] = make_float4(x, y, z, __int_as_float(i));
    }
}

// ---------------------------------------------------------------------------
// Merged ball query + attention. Warp per anchor (cell-sorted order).
// Phase 1: scan 9 contiguous spans of g_pts (coalesced float4), collect hits.
// Phase 2: slot selection (fast path hcnt<=32: raw set + min-index padding;
//          slow path: warp rank-sort).
// Phase 3: attention with FACTORED exp: e = exp2(qa)·exp2(-ka); EQ computed
//          once per anchor, EK pre-stored per neighbor -> 4 FMUL per k, one
//          MUFU (rcp) per k instead of five.
// ---------------------------------------------------------------------------
__global__ void __launch_bounds__(256)
ballattn_kernel(float* __restrict__ out)
{
    constexpr unsigned FULL = 0xffffffffu;
    constexpr int CAP = 128;
    __shared__ int hbuf[8][CAP];
    __shared__ int sorted[8][KNN];

    const int warp = threadIdx.x >> 5;
    const int lane = threadIdx.x & 31;
    const int p    = blockIdx.x * 8 + warp;      // cell-sorted anchor position
    const int b    = p >> 12;

    const float4 a4 = g_pts[p];
    const float ax = a4.x, ay = a4.y, az = a4.z;
    const int row  = (b << 12) + __float_as_int(a4.w);
    int cx, cy, cz; cell_coords(ax, ay, az, cx, cy, cz);

    const int nbase = (B + b) * NC;
    const float4* cand = g_pts + (B + b) * 4096;

    const int x0 = max(cx - 1, 0), x1 = min(cx + 1, GC - 1);
    const int z0 = max(cz - 1, 0), z1 = min(cz + 1, GC - 1);
    const int y0 = max(cy - 1, 0), y1 = min(cy + 1, GC - 1);

    // --- Phase 1: collect hits ---
    int hcnt = 0;
    for (int z = z0; z <= z1; ++z) {
        for (int y = y0; y <= y1; ++y) {
            const int cA = nbase + z*64 + y*8 + x0;
            const int cB = nbase + z*64 + y*8 + x1;
            const int st = g_start[cA];
            const int en = g_start[cB] + g_cnt[cB];
            for (int j = st; j < en; j += 32) {
                const int q = j + lane;
                int m = 0; bool hit = false;
                if (q < en) {
                    const float4 c4 = cand[q];   // coalesced LDG.128
                    const float fx = c4.x - ax;
                    const float fy = c4.y - ay;
                    const float fz = c4.z - az;
                    hit = (fx*fx + fy*fy + fz*fz) < RAD2;
                    m = __float_as_int(c4.w);
                }
                const unsigned mk = __ballot_sync(FULL, hit);
                if (hit) {
                    const int pos = hcnt + __popc(mk & ((1u << lane) - 1u));
                    if (pos < CAP) hbuf[warp][pos] = m;
                }
                hcnt += __popc(mk);
            }
        }
    }
    __syncwarp(FULL);

    // --- Phase 2: slot selection ---
    int my_m;
    if (hcnt <= KNN) {
        const int v = (lane < hcnt) ? hbuf[warp][lane] : 0x7fffffff;
        const int mn = redux_min_s32(v);
        my_m = (lane < hcnt) ? v : ((hcnt > 0) ? mn : 0);
    } else {
        const int n = min(hcnt, CAP);
        const int rounds = (n + 31) >> 5;
        int v[4], rk[4];
#pragma unroll
        for (int r = 0; r < 4; ++r) {
            const int i = lane + 32*r;
            v[r]  = (i < n) ? hbuf[warp][i] : 0x7fffffff;
            rk[r] = 0;
        }
        for (int step = 0; step < 32; ++step) {
#pragma unroll
            for (int s = 0; s < 4; ++s) {
                if (s < rounds) {
                    const int u = __shfl_sync(FULL, v[s], step);
#pragma unroll
                    for (int r = 0; r < 4; ++r)
                        if (r < rounds) rk[r] += (u < v[r]);
                }
            }
        }
#pragma unroll
        for (int r = 0; r < 4; ++r) {
            const int i = lane + 32*r;
            if (i < n && rk[r] < KNN) sorted[warp][rk[r]] = v[r];
        }
        __syncwarp(FULL);
        my_m = sorted[warp][lane];
    }

    // --- Phase 3: attention ---
    const float4 qa = ((const float4*)(g_QA + (size_t)row * C))[lane];
    const float4 ad = ((const float4*)(g_AD + (size_t)row * C))[lane];
    const float* KNb = g_KN + (size_t)b * MPTS * (2*C);

    // EQ factor, once per anchor
    const float eq0 = ex2f(qa.x), eq1 = ex2f(qa.y);
    const float eq2 = ex2f(qa.z), eq3 = ex2f(qa.w);

    float4 o = make_float4(-3.4e38f, -3.4e38f, -3.4e38f, -3.4e38f);

#pragma unroll 4
    for (int k = 0; k < KNN; ++k) {
        const int m = __shfl_sync(FULL, my_m, k);
        const float4* base = (const float4*)(KNb + (size_t)m * (2*C));
        const float4 kv = base[lane];        // EK factors
        const float4 nv = base[32 + lane];   // ND

        const float e0 = eq0 * kv.x;
        const float e1 = eq1 * kv.y;
        const float e2 = eq2 * kv.z;
        const float e3 = eq3 * kv.w;

        float s = (e0 + e1) + (e2 + e3);
#pragma unroll
        for (int off = 16; off; off >>= 1)
            s += __shfl_xor_sync(FULL, s, off);

        const float inv = __fdividef(1.0f, s);
        o.x = fmaxf(o.x, (ad.x - nv.x) * (e0 * inv));
        o.y = fmaxf(o.y, (ad.y - nv.y) * (e1 * inv));
        o.z = fmaxf(o.z, (ad.z - nv.z) * (e2 * inv));
        o.w = fmaxf(o.w, (ad.w - nv.w) * (e3 * inv));
    }

    ((float4*)(out + (size_t)row * C))[lane] = o;
}

// ---------------------------------------------------------------------------
// Launch: side = precompute -> proj; main = gridbuild. Join -> merged kernel.
// ---------------------------------------------------------------------------
extern "C" void kernel_launch(void* const* d_in, const int* in_sizes, int n_in,
                              void* d_out, int out_size)
{
    const float* anchor   = (const float*)d_in[0];
    const float* neighbor = (const float*)d_in[1];
    const float* Wq = (const float*)d_in[2];
    const float* bq = (const float*)d_in[3];
    const float* Wk = (const float*)d_in[4];
    const float* bk = (const float*)d_in[5];
    const float* Wd = (const float*)d_in[6];
    const float* bd = (const float*)d_in[7];
    const float* Wa = (const float*)d_in[8];
    const float* ba = (const float*)d_in[9];
    float* out = (float*)d_out;

    static cudaStream_t s_side = nullptr;
    static cudaEvent_t  e_fork = nullptr, e_join = nullptr;
    if (s_side == nullptr) {
        cudaStreamCreateWithFlags(&s_side, cudaStreamNonBlocking);
        cudaEventCreateWithFlags(&e_fork, cudaEventDisableTiming);
        cudaEventCreateWithFlags(&e_join, cudaEventDisableTiming);
    }

    cudaEventRecord(e_fork, 0);
    cudaStreamWaitEvent(s_side, e_fork, 0);
    precompute_kernel<<<1, 128, 0, s_side>>>(Wq, bq, Wk, bk, Wa, ba);
    proj_kernel<<<1024, 256, 0, s_side>>>(anchor, neighbor, Wd, bd);
    cudaEventRecord(e_join, s_side);

    gridbuild_kernel<<<8, 512>>>(anchor, neighbor);

    cudaStreamWaitEvent(0, e_join, 0);
    ballattn_kernel<<<2048, 256>>>(out);
}